// round 2
// baseline (speedup 1.0000x reference)
#include <cuda_runtime.h>
#include <cuda_bf16.h>
#include <math.h>

// Problem constants
#define N_ROWS   1024
#define IN_F     2048
#define BOOKS    8
#define OUT_F    4096
#define LW       256
#define WORDS    256
#define SC       30.0f
#define MARGIN   0.5f
#define EPS      1e-12f

// Output layout: out1 [n, books, out_f], out2 same, xc [n, books, words]
#define OUT1_ELEMS ((size_t)N_ROWS * BOOKS * OUT_F)   // 33,554,432
#define OFF2       OUT1_ELEMS
#define OFF3       (2 * OUT1_ELEMS)

// Scratch (device globals; allocation is forbidden)
__device__ float g_wn [BOOKS * OUT_F * LW];    // 33.5 MB normalized weights
__device__ float g_xn [BOOKS * N_ROWS * LW];   //  8.4 MB normalized x
__device__ float g_sn [BOOKS * N_ROWS * LW];   //  8.4 MB normalized s
__device__ float g_cbT[BOOKS * WORDS * LW];    //  2.1 MB transposed codebooks [b][w][d]

// ---------------------------------------------------------------------------
// Kernel 1: row-normalize weight [books*out_f rows of 256]
// ---------------------------------------------------------------------------
__global__ void k_norm_w(const float* __restrict__ w) {
    int row = blockIdx.x;
    int tid = threadIdx.x;
    const float* src = w + (size_t)row * LW;
    float v = src[tid];
    float ss = v * v;
    #pragma unroll
    for (int off = 16; off; off >>= 1) ss += __shfl_xor_sync(0xffffffffu, ss, off);
    __shared__ float wsum[8];
    if ((tid & 31) == 0) wsum[tid >> 5] = ss;
    __syncthreads();
    if (tid < 8) {
        float t = wsum[tid];
        #pragma unroll
        for (int off = 4; off; off >>= 1) t += __shfl_xor_sync(0xffu, t, off);
        if (tid == 0) wsum[0] = t;
    }
    __syncthreads();
    float inv = 1.0f / fmaxf(sqrtf(wsum[0]), EPS);
    g_wn[(size_t)row * LW + tid] = v * inv;
}

// ---------------------------------------------------------------------------
// Kernel 2: transpose codebooks: cbT[b][w][d] = cb[b][d][w]
// ---------------------------------------------------------------------------
__global__ void k_transpose_cb(const float* __restrict__ cb) {
    __shared__ float t[32][33];
    int b  = blockIdx.z;
    int d0 = blockIdx.x * 32;
    int w0 = blockIdx.y * 32;
    const float* src = cb    + (size_t)b * LW * WORDS;
    float*       dst = g_cbT + (size_t)b * LW * WORDS;
    for (int i = threadIdx.y; i < 32; i += 8)
        t[i][threadIdx.x] = src[(size_t)(d0 + i) * WORDS + w0 + threadIdx.x];
    __syncthreads();
    for (int i = threadIdx.y; i < 32; i += 8)
        dst[(size_t)(w0 + i) * LW + d0 + threadIdx.x] = t[threadIdx.x][i];
}

// ---------------------------------------------------------------------------
// Kernel 3 (fused): per (book, 16-row tile):
//   logits = x @ mlp ; softmax -> xc (written to out region 3)
//   s      = xc @ cbT
//   xn = normalize(x), sn = normalize(s)
// 256 threads; thread t owns output column t.
// ---------------------------------------------------------------------------
__global__ void k_features(const float* __restrict__ input,
                           const float* __restrict__ mlp,
                           float* __restrict__ out) {
    int bid = blockIdx.x;
    int b   = bid >> 6;            // book
    int n0  = (bid & 63) * 16;     // base row
    int tid = threadIdx.x;

    __shared__ __align__(16) float xs[16][256];  // x tile
    __shared__ __align__(16) float ls[16][256];  // logits -> xc -> s
    __shared__ float rowinv_s[16], rowinv_x[16];

    const float* mlp_b = mlp   + (size_t)b * LW * WORDS;
    const float* cbT_b = g_cbT + (size_t)b * WORDS * LW;

    // load x tile (row n0+i, this book's 256-chunk)
    #pragma unroll
    for (int i = 0; i < 16; i++)
        xs[i][tid] = input[(size_t)(n0 + i) * IN_F + b * LW + tid];
    __syncthreads();

    // ---- logits[r][w=tid] = sum_d xs[r][d] * mlp[d][w]
    float acc[16];
    #pragma unroll
    for (int i = 0; i < 16; i++) acc[i] = 0.0f;
    for (int d = 0; d < LW; d += 4) {
        float m0 = mlp_b[(size_t)(d + 0) * WORDS + tid];
        float m1 = mlp_b[(size_t)(d + 1) * WORDS + tid];
        float m2 = mlp_b[(size_t)(d + 2) * WORDS + tid];
        float m3 = mlp_b[(size_t)(d + 3) * WORDS + tid];
        #pragma unroll
        for (int r = 0; r < 16; r++) {
            float4 xv = *(const float4*)&xs[r][d];
            acc[r] += xv.x * m0 + xv.y * m1 + xv.z * m2 + xv.w * m3;
        }
    }
    #pragma unroll
    for (int r = 0; r < 16; r++) ls[r][tid] = acc[r];
    __syncthreads();

    // ---- softmax per row; warp wi handles rows wi and wi+8
    int wi = tid >> 5, lane = tid & 31;
    #pragma unroll
    for (int rr = 0; rr < 2; rr++) {
        int r = wi + rr * 8;
        float mx = -1e30f;
        #pragma unroll
        for (int c = 0; c < 256; c += 32) mx = fmaxf(mx, ls[r][lane + c]);
        #pragma unroll
        for (int off = 16; off; off >>= 1) mx = fmaxf(mx, __shfl_xor_sync(0xffffffffu, mx, off));
        float sm = 0.0f;
        #pragma unroll
        for (int c = 0; c < 256; c += 32) {
            float e = expf(ls[r][lane + c] - mx);
            ls[r][lane + c] = e;
            sm += e;
        }
        #pragma unroll
        for (int off = 16; off; off >>= 1) sm += __shfl_xor_sync(0xffffffffu, sm, off);
        float inv = 1.0f / sm;
        #pragma unroll
        for (int c = 0; c < 256; c += 32) ls[r][lane + c] *= inv;
    }
    __syncthreads();

    // write xc_soft: [n, b, w]
    #pragma unroll
    for (int i = 0; i < 16; i++)
        out[OFF3 + (size_t)(n0 + i) * (BOOKS * WORDS) + b * WORDS + tid] = ls[i][tid];

    // ---- s[r][d=tid] = sum_w xc[r][w] * cbT[w][d]
    float acc2[16];
    #pragma unroll
    for (int i = 0; i < 16; i++) acc2[i] = 0.0f;
    for (int w = 0; w < WORDS; w += 4) {
        float c0 = cbT_b[(size_t)(w + 0) * LW + tid];
        float c1 = cbT_b[(size_t)(w + 1) * LW + tid];
        float c2 = cbT_b[(size_t)(w + 2) * LW + tid];
        float c3 = cbT_b[(size_t)(w + 3) * LW + tid];
        #pragma unroll
        for (int r = 0; r < 16; r++) {
            float4 xv = *(const float4*)&ls[r][w];
            acc2[r] += xv.x * c0 + xv.y * c1 + xv.z * c2 + xv.w * c3;
        }
    }
    __syncthreads();            // done reading ls as xc
    #pragma unroll
    for (int r = 0; r < 16; r++) ls[r][tid] = acc2[r];   // ls now holds s
    __syncthreads();

    // ---- row norms of s and x; warp wi handles rows wi, wi+8
    #pragma unroll
    for (int rr = 0; rr < 2; rr++) {
        int r = wi + rr * 8;
        float s2 = 0.0f, x2 = 0.0f;
        #pragma unroll
        for (int c = 0; c < 256; c += 32) {
            float sv = ls[r][lane + c]; s2 += sv * sv;
            float xv = xs[r][lane + c]; x2 += xv * xv;
        }
        #pragma unroll
        for (int off = 16; off; off >>= 1) {
            s2 += __shfl_xor_sync(0xffffffffu, s2, off);
            x2 += __shfl_xor_sync(0xffffffffu, x2, off);
        }
        if (lane == 0) {
            rowinv_s[r] = 1.0f / fmaxf(sqrtf(s2), EPS);
            rowinv_x[r] = 1.0f / fmaxf(sqrtf(x2), EPS);
        }
    }
    __syncthreads();
    #pragma unroll
    for (int i = 0; i < 16; i++) {
        size_t o = ((size_t)b * N_ROWS + n0 + i) * LW + tid;
        g_sn[o] = ls[i][tid] * rowinv_s[i];
        g_xn[o] = xs[i][tid] * rowinv_x[i];
    }
}

// ---------------------------------------------------------------------------
// Kernel 4: dual batched GEMM + epilogue.
// Per block: book b, 64 rows (n) x 64 cols (out_f), K=256.
// Computes cos(xn,wn) and cos(sn,wn) sharing the wn tile, then
// out = SC*(clip(cos,-1,1) - (o==label[n])*MARGIN), float4 stores.
// label is INT32 (JAX x64 disabled -> int64 request silently yields int32).
// ---------------------------------------------------------------------------
#define KT 16
__global__ void k_gemm(const int* __restrict__ label,
                       float* __restrict__ out) {
    int b  = blockIdx.z;
    int mt = blockIdx.y;
    int nt = blockIdx.x;
    int tid = threadIdx.x;

    const float* A1 = g_xn + ((size_t)b * N_ROWS + mt * 64) * LW;
    const float* A2 = g_sn + ((size_t)b * N_ROWS + mt * 64) * LW;
    const float* B  = g_wn + ((size_t)b * OUT_F  + nt * 64) * LW;

    __shared__ float As1[KT][65];
    __shared__ float As2[KT][65];
    __shared__ float Bs [KT][65];
    __shared__ int   lbl[64];

    if (tid < 64) lbl[tid] = label[mt * 64 + tid];

    int lr = tid >> 2;             // 0..63 row in tile for loads
    int lk = (tid & 3) * 4;        // k sub-offset 0/4/8/12
    int tx = tid & 15;             // 0..15 -> cols tx*4..+3
    int ty = tid >> 4;             // 0..15 -> rows ty*4..+3

    float acc1[4][4], acc2[4][4];
    #pragma unroll
    for (int i = 0; i < 4; i++)
        #pragma unroll
        for (int j = 0; j < 4; j++) { acc1[i][j] = 0.0f; acc2[i][j] = 0.0f; }

    for (int k0 = 0; k0 < LW; k0 += KT) {
        float4 a1v = *(const float4*)(A1 + (size_t)lr * LW + k0 + lk);
        float4 a2v = *(const float4*)(A2 + (size_t)lr * LW + k0 + lk);
        float4 bv  = *(const float4*)(B  + (size_t)lr * LW + k0 + lk);
        __syncthreads();   // previous tile's compute done
        As1[lk + 0][lr] = a1v.x; As1[lk + 1][lr] = a1v.y;
        As1[lk + 2][lr] = a1v.z; As1[lk + 3][lr] = a1v.w;
        As2[lk + 0][lr] = a2v.x; As2[lk + 1][lr] = a2v.y;
        As2[lk + 2][lr] = a2v.z; As2[lk + 3][lr] = a2v.w;
        Bs [lk + 0][lr] = bv.x;  Bs [lk + 1][lr] = bv.y;
        Bs [lk + 2][lr] = bv.z;  Bs [lk + 3][lr] = bv.w;
        __syncthreads();
        #pragma unroll
        for (int kk = 0; kk < KT; kk++) {
            float bf[4], a1f[4], a2f[4];
            #pragma unroll
            for (int j = 0; j < 4; j++) bf[j]  = Bs [kk][tx * 4 + j];
            #pragma unroll
            for (int i = 0; i < 4; i++) { a1f[i] = As1[kk][ty * 4 + i];
                                          a2f[i] = As2[kk][ty * 4 + i]; }
            #pragma unroll
            for (int i = 0; i < 4; i++)
                #pragma unroll
                for (int j = 0; j < 4; j++) {
                    acc1[i][j] += a1f[i] * bf[j];
                    acc2[i][j] += a2f[i] * bf[j];
                }
        }
    }
    __syncthreads();   // lbl visible (also covered by loop syncs)

    int coff = nt * 64 + tx * 4;
    #pragma unroll
    for (int i = 0; i < 4; i++) {
        int n  = mt * 64 + ty * 4 + i;
        int lv = lbl[ty * 4 + i];
        size_t base = (size_t)n * (BOOKS * OUT_F) + (size_t)b * OUT_F + coff;
        float4 v1, v2;
        float* pv1 = &v1.x; float* pv2 = &v2.x;
        #pragma unroll
        for (int j = 0; j < 4; j++) {
            int o = coff + j;
            float m = (o == lv) ? MARGIN : 0.0f;
            float c1 = fminf(fmaxf(acc1[i][j], -1.0f), 1.0f);
            float c2 = fminf(fmaxf(acc2[i][j], -1.0f), 1.0f);
            pv1[j] = SC * (c1 - m);
            pv2[j] = SC * (c2 - m);
        }
        *(float4*)(out + base)        = v1;
        *(float4*)(out + OFF2 + base) = v2;
    }
}

// ---------------------------------------------------------------------------
extern "C" void kernel_launch(void* const* d_in, const int* in_sizes, int n_in,
                              void* d_out, int out_size) {
    const float* input  = (const float*)d_in[0];
    const int*   label  = (const int*)d_in[1];
    const float* weight = (const float*)d_in[2];
    const float* mlp    = (const float*)d_in[3];
    const float* cb     = (const float*)d_in[4];
    float*       out    = (float*)d_out;
    (void)in_sizes; (void)n_in; (void)out_size;

    // 1. normalize weights -> g_wn
    k_norm_w<<<BOOKS * OUT_F, 256>>>(weight);
    // 2. transpose codebooks -> g_cbT
    k_transpose_cb<<<dim3(LW / 32, WORDS / 32, BOOKS), dim3(32, 8)>>>(cb);
    // 3. fused features: xc (to out), g_xn, g_sn
    k_features<<<BOOKS * (N_ROWS / 16), 256>>>(input, mlp, out);
    // 4. dual GEMM + epilogue -> out1, out2
    k_gemm<<<dim3(OUT_F / 64, N_ROWS / 64, BOOKS), 256>>>(label, out);
}

// round 4
// speedup vs baseline: 2.1637x; 2.1637x over previous
#include <cuda_runtime.h>
#include <cuda_bf16.h>
#include <mma.h>
#include <math.h>
#include <stdint.h>

using namespace nvcuda;

// Problem constants
#define N_ROWS   1024
#define IN_F     2048
#define BOOKS    8
#define OUT_F    4096
#define LW       256
#define WORDS    256
#define SC       30.0f
#define MARGIN   0.5f
#define EPS      1e-12f

#define OUT1_ELEMS ((size_t)N_ROWS * BOOKS * OUT_F)
#define OFF2       OUT1_ELEMS
#define OFF3       (2 * OUT1_ELEMS)

// bf16 hi/lo split operands (emulated fp32 via 3 bf16 MMAs)
__device__ __nv_bfloat16 g_xh[BOOKS * N_ROWS * LW];
__device__ __nv_bfloat16 g_xl[BOOKS * N_ROWS * LW];
__device__ __nv_bfloat16 g_sh[BOOKS * N_ROWS * LW];
__device__ __nv_bfloat16 g_sl[BOOKS * N_ROWS * LW];
__device__ __nv_bfloat16 g_wh[BOOKS * OUT_F * LW];
__device__ __nv_bfloat16 g_wl[BOOKS * OUT_F * LW];
__device__ float g_cbT[BOOKS * WORDS * LW];

__device__ __forceinline__ uint32_t smem_u32(const void* p) {
    uint32_t a;
    asm("{ .reg .u64 t; cvta.to.shared.u64 t, %1; cvt.u32.u64 %0, t; }"
        : "=r"(a) : "l"(p));
    return a;
}

#define CP_ASYNC16(dst, src) \
    asm volatile("cp.async.cg.shared.global [%0], [%1], 16;" \
        :: "r"(dst), "l"(src) : "memory")
#define CP_COMMIT() asm volatile("cp.async.commit_group;" ::: "memory")
#define CP_WAIT(n)  asm volatile("cp.async.wait_group %0;" :: "n"(n) : "memory")

__device__ __forceinline__ void split_bf16(float v, __nv_bfloat16& h, __nv_bfloat16& l) {
    h = __float2bfloat16(v);
    l = __float2bfloat16(v - __bfloat162float(h));
}

// ---------------------------------------------------------------------------
// Kernel 1: row-normalize weight -> bf16 hi/lo
// ---------------------------------------------------------------------------
__global__ void k_norm_w(const float* __restrict__ w) {
    int row = blockIdx.x;
    int tid = threadIdx.x;
    float v = w[(size_t)row * LW + tid];
    float ss = v * v;
    #pragma unroll
    for (int off = 16; off; off >>= 1) ss += __shfl_xor_sync(0xffffffffu, ss, off);
    __shared__ float wsum[8];
    if ((tid & 31) == 0) wsum[tid >> 5] = ss;
    __syncthreads();
    if (tid < 8) {
        float t = wsum[tid];
        #pragma unroll
        for (int off = 4; off; off >>= 1) t += __shfl_xor_sync(0xffu, t, off);
        if (tid == 0) wsum[0] = t;
    }
    __syncthreads();
    float inv = 1.0f / fmaxf(sqrtf(wsum[0]), EPS);
    float nv = v * inv;
    __nv_bfloat16 h, l;
    split_bf16(nv, h, l);
    g_wh[(size_t)row * LW + tid] = h;
    g_wl[(size_t)row * LW + tid] = l;
}

// ---------------------------------------------------------------------------
// Kernel 2: transpose codebooks
// ---------------------------------------------------------------------------
__global__ void k_transpose_cb(const float* __restrict__ cb) {
    __shared__ float t[32][33];
    int b  = blockIdx.z;
    int d0 = blockIdx.x * 32;
    int w0 = blockIdx.y * 32;
    const float* src = cb    + (size_t)b * LW * WORDS;
    float*       dst = g_cbT + (size_t)b * LW * WORDS;
    for (int i = threadIdx.y; i < 32; i += 8)
        t[i][threadIdx.x] = src[(size_t)(d0 + i) * WORDS + w0 + threadIdx.x];
    __syncthreads();
    for (int i = threadIdx.y; i < 32; i += 8)
        dst[(size_t)(w0 + i) * LW + d0 + threadIdx.x] = t[threadIdx.x][i];
}

// ---------------------------------------------------------------------------
// Kernel 3 (fused): logits->softmax->xc (to out), s=xc@cbT, normalize x & s,
// write bf16 hi/lo splits of xn, sn.
// ---------------------------------------------------------------------------
__global__ void k_features(const float* __restrict__ input,
                           const float* __restrict__ mlp,
                           float* __restrict__ out) {
    int bid = blockIdx.x;
    int b   = bid >> 6;
    int n0  = (bid & 63) * 16;
    int tid = threadIdx.x;

    __shared__ __align__(16) float xs[16][256];
    __shared__ __align__(16) float ls[16][256];
    __shared__ float rowinv_s[16], rowinv_x[16];

    const float* mlp_b = mlp   + (size_t)b * LW * WORDS;
    const float* cbT_b = g_cbT + (size_t)b * WORDS * LW;

    #pragma unroll
    for (int i = 0; i < 16; i++)
        xs[i][tid] = input[(size_t)(n0 + i) * IN_F + b * LW + tid];
    __syncthreads();

    float acc[16];
    #pragma unroll
    for (int i = 0; i < 16; i++) acc[i] = 0.0f;
    for (int d = 0; d < LW; d += 4) {
        float m0 = mlp_b[(size_t)(d + 0) * WORDS + tid];
        float m1 = mlp_b[(size_t)(d + 1) * WORDS + tid];
        float m2 = mlp_b[(size_t)(d + 2) * WORDS + tid];
        float m3 = mlp_b[(size_t)(d + 3) * WORDS + tid];
        #pragma unroll
        for (int r = 0; r < 16; r++) {
            float4 xv = *(const float4*)&xs[r][d];
            acc[r] += xv.x * m0 + xv.y * m1 + xv.z * m2 + xv.w * m3;
        }
    }
    #pragma unroll
    for (int r = 0; r < 16; r++) ls[r][tid] = acc[r];
    __syncthreads();

    int wi = tid >> 5, lane = tid & 31;
    #pragma unroll
    for (int rr = 0; rr < 2; rr++) {
        int r = wi + rr * 8;
        float mx = -1e30f;
        #pragma unroll
        for (int c = 0; c < 256; c += 32) mx = fmaxf(mx, ls[r][lane + c]);
        #pragma unroll
        for (int off = 16; off; off >>= 1) mx = fmaxf(mx, __shfl_xor_sync(0xffffffffu, mx, off));
        float sm = 0.0f;
        #pragma unroll
        for (int c = 0; c < 256; c += 32) {
            float e = expf(ls[r][lane + c] - mx);
            ls[r][lane + c] = e;
            sm += e;
        }
        #pragma unroll
        for (int off = 16; off; off >>= 1) sm += __shfl_xor_sync(0xffffffffu, sm, off);
        float inv = 1.0f / sm;
        #pragma unroll
        for (int c = 0; c < 256; c += 32) ls[r][lane + c] *= inv;
    }
    __syncthreads();

    #pragma unroll
    for (int i = 0; i < 16; i++)
        out[OFF3 + (size_t)(n0 + i) * (BOOKS * WORDS) + b * WORDS + tid] = ls[i][tid];

    float acc2[16];
    #pragma unroll
    for (int i = 0; i < 16; i++) acc2[i] = 0.0f;
    for (int w = 0; w < WORDS; w += 4) {
        float c0 = cbT_b[(size_t)(w + 0) * LW + tid];
        float c1 = cbT_b[(size_t)(w + 1) * LW + tid];
        float c2 = cbT_b[(size_t)(w + 2) * LW + tid];
        float c3 = cbT_b[(size_t)(w + 3) * LW + tid];
        #pragma unroll
        for (int r = 0; r < 16; r++) {
            float4 xv = *(const float4*)&ls[r][w];
            acc2[r] += xv.x * c0 + xv.y * c1 + xv.z * c2 + xv.w * c3;
        }
    }
    __syncthreads();
    #pragma unroll
    for (int r = 0; r < 16; r++) ls[r][tid] = acc2[r];
    __syncthreads();

    #pragma unroll
    for (int rr = 0; rr < 2; rr++) {
        int r = wi + rr * 8;
        float s2 = 0.0f, x2 = 0.0f;
        #pragma unroll
        for (int c = 0; c < 256; c += 32) {
            float sv = ls[r][lane + c]; s2 += sv * sv;
            float xv = xs[r][lane + c]; x2 += xv * xv;
        }
        #pragma unroll
        for (int off = 16; off; off >>= 1) {
            s2 += __shfl_xor_sync(0xffffffffu, s2, off);
            x2 += __shfl_xor_sync(0xffffffffu, x2, off);
        }
        if (lane == 0) {
            rowinv_s[r] = 1.0f / fmaxf(sqrtf(s2), EPS);
            rowinv_x[r] = 1.0f / fmaxf(sqrtf(x2), EPS);
        }
    }
    __syncthreads();
    #pragma unroll
    for (int i = 0; i < 16; i++) {
        size_t o = ((size_t)b * N_ROWS + n0 + i) * LW + tid;
        float sv = ls[i][tid] * rowinv_s[i];
        float xv = xs[i][tid] * rowinv_x[i];
        __nv_bfloat16 h, l;
        split_bf16(sv, h, l); g_sh[o] = h; g_sl[o] = l;
        split_bf16(xv, h, l); g_xh[o] = h; g_xl[o] = l;
    }
}

// ---------------------------------------------------------------------------
// Kernel 4: WMMA bf16x3 dual GEMM + fused epilogue.
// Per CTA: book b, 128 n-rows, 128 out_f cols; K=256 in 4 chunks of 64,
// cp.async double-buffered. acc1 = xh*wh + xh*wl + xl*wh; acc2 likewise with s.
// ---------------------------------------------------------------------------
#define LDT      72                       // bf16 elems per tile row (144B, 16B-aligned)
#define TILE_E   (128 * LDT)              // 9216 elems
#define TILE_B   (TILE_E * 2)             // 18432 bytes
#define STAGE_E  (6 * TILE_E)
#define STAGE_B  (6 * TILE_B)             // 110592
#define DYN_SMEM (2 * STAGE_B)            // 221184
#define DPITCH   136                      // fp32 epilogue pitch
#define REG2     (128 * DPITCH)

__global__ void __launch_bounds__(256, 1) k_gemm_wm(const int* __restrict__ label,
                                                    float* __restrict__ out) {
    extern __shared__ __align__(16) char dsm[];
    __nv_bfloat16* smt = (__nv_bfloat16*)dsm;
    __shared__ int s_lbl[128];

    int tid = threadIdx.x;
    int wid = tid >> 5, lane = tid & 31;
    int nt = blockIdx.x, mt = blockIdx.y, b = blockIdx.z;
    uint32_t smbase = smem_u32(dsm);

    if (tid < 128) s_lbl[tid] = label[mt * 128 + tid];

    const char* pXH = (const char*)(g_xh + ((size_t)b * N_ROWS + mt * 128) * LW);
    const char* pXL = (const char*)(g_xl + ((size_t)b * N_ROWS + mt * 128) * LW);
    const char* pSH = (const char*)(g_sh + ((size_t)b * N_ROWS + mt * 128) * LW);
    const char* pSL = (const char*)(g_sl + ((size_t)b * N_ROWS + mt * 128) * LW);
    const char* pWH = (const char*)(g_wh + ((size_t)b * OUT_F  + nt * 128) * LW);
    const char* pWL = (const char*)(g_wl + ((size_t)b * OUT_F  + nt * 128) * LW);

    // Each source row = 256 bf16 = 512B; chunk c covers bytes [c*128, c*128+128).
#define LD1TILE(ptr, t, c_, st_) { \
    _Pragma("unroll") for (int j = 0; j < 4; j++) { \
        int u = j * 256 + tid; int row = u >> 3, seg = u & 7; \
        uint32_t dst = smbase + (st_) * STAGE_B + (t) * TILE_B + row * 144 + seg * 16; \
        const char* src = (ptr) + (size_t)row * 512 + (c_) * 128 + seg * 16; \
        CP_ASYNC16(dst, src); } }
#define LOAD_CHUNK(c_, st_) { \
    LD1TILE(pXH, 0, c_, st_); LD1TILE(pXL, 1, c_, st_); \
    LD1TILE(pSH, 2, c_, st_); LD1TILE(pSL, 3, c_, st_); \
    LD1TILE(pWH, 4, c_, st_); LD1TILE(pWL, 5, c_, st_); \
    CP_COMMIT(); }

    wmma::fragment<wmma::accumulator, 16, 16, 16, float> acc1[2][4], acc2[2][4];
    #pragma unroll
    for (int im = 0; im < 2; im++)
        #pragma unroll
        for (int jn = 0; jn < 4; jn++) {
            wmma::fill_fragment(acc1[im][jn], 0.0f);
            wmma::fill_fragment(acc2[im][jn], 0.0f);
        }

    int wm = wid & 3;       // 4 m-blocks of 32 rows
    int wn = wid >> 2;      // 2 n-blocks of 64 cols

    LOAD_CHUNK(0, 0);
    LOAD_CHUNK(1, 1);

    #pragma unroll
    for (int c = 0; c < 4; c++) {
        if (c < 3) { CP_WAIT(1); } else { CP_WAIT(0); }
        __syncthreads();
        {
            int st = c & 1;
            const __nv_bfloat16* base = smt + st * STAGE_E;
            const __nv_bfloat16* tXH = base;
            const __nv_bfloat16* tXL = base + TILE_E;
            const __nv_bfloat16* tSH = base + 2 * TILE_E;
            const __nv_bfloat16* tSL = base + 3 * TILE_E;
            const __nv_bfloat16* tWH = base + 4 * TILE_E;
            const __nv_bfloat16* tWL = base + 5 * TILE_E;
            #pragma unroll
            for (int k = 0; k < 4; k++) {
                wmma::fragment<wmma::matrix_a, 16, 16, 16, __nv_bfloat16, wmma::row_major>
                    axh[2], axl[2], ash[2], asl[2];
                #pragma unroll
                for (int im = 0; im < 2; im++) {
                    int r0 = wm * 32 + im * 16;
                    wmma::load_matrix_sync(axh[im], tXH + r0 * LDT + k * 16, LDT);
                    wmma::load_matrix_sync(axl[im], tXL + r0 * LDT + k * 16, LDT);
                    wmma::load_matrix_sync(ash[im], tSH + r0 * LDT + k * 16, LDT);
                    wmma::load_matrix_sync(asl[im], tSL + r0 * LDT + k * 16, LDT);
                }
                #pragma unroll
                for (int jn = 0; jn < 4; jn++) {
                    int c0 = wn * 64 + jn * 16;
                    wmma::fragment<wmma::matrix_b, 16, 16, 16, __nv_bfloat16, wmma::col_major> bwh, bwl;
                    wmma::load_matrix_sync(bwh, tWH + c0 * LDT + k * 16, LDT);
                    wmma::load_matrix_sync(bwl, tWL + c0 * LDT + k * 16, LDT);
                    #pragma unroll
                    for (int im = 0; im < 2; im++) {
                        wmma::mma_sync(acc1[im][jn], axh[im], bwh, acc1[im][jn]);
                        wmma::mma_sync(acc1[im][jn], axh[im], bwl, acc1[im][jn]);
                        wmma::mma_sync(acc1[im][jn], axl[im], bwh, acc1[im][jn]);
                        wmma::mma_sync(acc2[im][jn], ash[im], bwh, acc2[im][jn]);
                        wmma::mma_sync(acc2[im][jn], ash[im], bwl, acc2[im][jn]);
                        wmma::mma_sync(acc2[im][jn], asl[im], bwh, acc2[im][jn]);
                    }
                }
            }
        }
        __syncthreads();
        if (c + 2 < 4) { LOAD_CHUNK(c + 2, c & 1); }
    }

    // Stage accumulators to smem, then coalesced epilogue with clip/margin/scale
    float* D = (float*)dsm;
    #pragma unroll
    for (int im = 0; im < 2; im++)
        #pragma unroll
        for (int jn = 0; jn < 4; jn++) {
            int r0 = wm * 32 + im * 16;
            int c0 = wn * 64 + jn * 16;
            wmma::store_matrix_sync(D + (size_t)r0 * DPITCH + c0, acc1[im][jn],
                                    DPITCH, wmma::mem_row_major);
            wmma::store_matrix_sync(D + REG2 + (size_t)r0 * DPITCH + c0, acc2[im][jn],
                                    DPITCH, wmma::mem_row_major);
        }
    __syncthreads();

    {
        int colq = lane;
        for (int r0 = wid; r0 < 128; r0 += 8) {
            int lv = s_lbl[r0];
            int o0 = nt * 128 + colq * 4;
            size_t basep = (size_t)(mt * 128 + r0) * (BOOKS * OUT_F) + (size_t)b * OUT_F + o0;
            float4 v1 = *(float4*)&D[(size_t)r0 * DPITCH + colq * 4];
            float4 v2 = *(float4*)&D[REG2 + (size_t)r0 * DPITCH + colq * 4];
            float* p1 = &v1.x; float* p2 = &v2.x;
            #pragma unroll
            for (int j = 0; j < 4; j++) {
                float m = (o0 + j == lv) ? MARGIN : 0.0f;
                p1[j] = SC * (fminf(fmaxf(p1[j], -1.0f), 1.0f) - m);
                p2[j] = SC * (fminf(fmaxf(p2[j], -1.0f), 1.0f) - m);
            }
            *(float4*)(out + basep)        = v1;
            *(float4*)(out + OFF2 + basep) = v2;
        }
    }
}

// ---------------------------------------------------------------------------
extern "C" void kernel_launch(void* const* d_in, const int* in_sizes, int n_in,
                              void* d_out, int out_size) {
    const float* input  = (const float*)d_in[0];
    const int*   label  = (const int*)d_in[1];
    const float* weight = (const float*)d_in[2];
    const float* mlp    = (const float*)d_in[3];
    const float* cb     = (const float*)d_in[4];
    float*       out    = (float*)d_out;
    (void)in_sizes; (void)n_in; (void)out_size;

    cudaFuncSetAttribute(k_gemm_wm, cudaFuncAttributeMaxDynamicSharedMemorySize, DYN_SMEM);

    k_norm_w<<<BOOKS * OUT_F, 256>>>(weight);
    k_transpose_cb<<<dim3(LW / 32, WORDS / 32, BOOKS), dim3(32, 8)>>>(cb);
    k_features<<<BOOKS * (N_ROWS / 16), 256>>>(input, mlp, out);
    k_gemm_wm<<<dim3(OUT_F / 128, N_ROWS / 128, BOOKS), 256, DYN_SMEM>>>(label, out);
}

// round 5
// speedup vs baseline: 2.5422x; 1.1749x over previous
#include <cuda_runtime.h>
#include <cuda_bf16.h>
#include <mma.h>
#include <math.h>
#include <stdint.h>

using namespace nvcuda;

// Problem constants
#define N_ROWS   1024
#define IN_F     2048
#define BOOKS    8
#define OUT_F    4096
#define LW       256
#define WORDS    256
#define SC       30.0f
#define MARGIN   0.5f
#define EPS      1e-12f

#define OUT1_ELEMS ((size_t)N_ROWS * BOOKS * OUT_F)
#define OFF2       OUT1_ELEMS
#define OFF3       (2 * OUT1_ELEMS)

// bf16 hi/lo split operands (emulated fp32 via 3 bf16 MMAs)
__device__ __nv_bfloat16 g_xh[BOOKS * N_ROWS * LW];
__device__ __nv_bfloat16 g_xl[BOOKS * N_ROWS * LW];
__device__ __nv_bfloat16 g_sh[BOOKS * N_ROWS * LW];
__device__ __nv_bfloat16 g_sl[BOOKS * N_ROWS * LW];
__device__ __nv_bfloat16 g_wh[BOOKS * OUT_F * LW];
__device__ __nv_bfloat16 g_wl[BOOKS * OUT_F * LW];
__device__ __nv_bfloat16 g_mh[BOOKS * LW * WORDS];
__device__ __nv_bfloat16 g_ml[BOOKS * LW * WORDS];
__device__ __nv_bfloat16 g_cbTh[BOOKS * WORDS * LW];
__device__ __nv_bfloat16 g_cbTl[BOOKS * WORDS * LW];

__device__ __forceinline__ uint32_t smem_u32(const void* p) {
    uint32_t a;
    asm("{ .reg .u64 t; cvta.to.shared.u64 t, %1; cvt.u32.u64 %0, t; }"
        : "=r"(a) : "l"(p));
    return a;
}

#define CP_ASYNC16(dst, src) \
    asm volatile("cp.async.cg.shared.global [%0], [%1], 16;" \
        :: "r"(dst), "l"(src) : "memory")
#define CP_COMMIT() asm volatile("cp.async.commit_group;" ::: "memory")
#define CP_WAIT(n)  asm volatile("cp.async.wait_group %0;" :: "n"(n) : "memory")

__device__ __forceinline__ void split_bf16(float v, __nv_bfloat16& h, __nv_bfloat16& l) {
    h = __float2bfloat16(v);
    l = __float2bfloat16(v - __bfloat162float(h));
}

// ---------------------------------------------------------------------------
// Kernel 1: row-normalize weight -> bf16 hi/lo. One warp per 256-elem row.
// ---------------------------------------------------------------------------
__global__ void __launch_bounds__(256) k_norm_w(const float* __restrict__ w) {
    int row  = blockIdx.x * 8 + (threadIdx.x >> 5);
    int lane = threadIdx.x & 31;
    const float* src = w + (size_t)row * LW + lane * 8;
    float4 a = *(const float4*)src;
    float4 c = *(const float4*)(src + 4);
    float ss = a.x*a.x + a.y*a.y + a.z*a.z + a.w*a.w
             + c.x*c.x + c.y*c.y + c.z*c.z + c.w*c.w;
    #pragma unroll
    for (int off = 16; off; off >>= 1) ss += __shfl_xor_sync(0xffffffffu, ss, off);
    float inv = 1.0f / fmaxf(sqrtf(ss), EPS);
    __align__(16) __nv_bfloat16 h8[8], l8[8];
    float v[8] = {a.x, a.y, a.z, a.w, c.x, c.y, c.z, c.w};
    #pragma unroll
    for (int j = 0; j < 8; j++) split_bf16(v[j] * inv, h8[j], l8[j]);
    *(uint4*)(g_wh + (size_t)row * LW + lane * 8) = *(uint4*)h8;
    *(uint4*)(g_wl + (size_t)row * LW + lane * 8) = *(uint4*)l8;
}

// ---------------------------------------------------------------------------
// Kernel 2a: elementwise split of mlp -> g_mh/g_ml
// ---------------------------------------------------------------------------
__global__ void __launch_bounds__(256) k_split_mlp(const float* __restrict__ m) {
    size_t i = ((size_t)blockIdx.x * 256 + threadIdx.x) * 4;
    float4 v = *(const float4*)(m + i);
    __align__(8) __nv_bfloat16 h4[4], l4[4];
    split_bf16(v.x, h4[0], l4[0]); split_bf16(v.y, h4[1], l4[1]);
    split_bf16(v.z, h4[2], l4[2]); split_bf16(v.w, h4[3], l4[3]);
    *(uint2*)(g_mh + i) = *(uint2*)h4;
    *(uint2*)(g_ml + i) = *(uint2*)l4;
}

// ---------------------------------------------------------------------------
// Kernel 2b: transpose codebooks + split: cbT[b][w][d] = cb[b][d][w]
// ---------------------------------------------------------------------------
__global__ void k_transpose_cb(const float* __restrict__ cb) {
    __shared__ float t[32][33];
    int b  = blockIdx.z;
    int d0 = blockIdx.x * 32;
    int w0 = blockIdx.y * 32;
    const float* src = cb + (size_t)b * LW * WORDS;
    for (int i = threadIdx.y; i < 32; i += 8)
        t[i][threadIdx.x] = src[(size_t)(d0 + i) * WORDS + w0 + threadIdx.x];
    __syncthreads();
    for (int i = threadIdx.y; i < 32; i += 8) {
        float v = t[threadIdx.x][i];
        __nv_bfloat16 h, l;
        split_bf16(v, h, l);
        size_t o = (size_t)b * WORDS * LW + (size_t)(w0 + i) * LW + d0 + threadIdx.x;
        g_cbTh[o] = h;
        g_cbTl[o] = l;
    }
}

// ---------------------------------------------------------------------------
// Kernel 3: WMMA bf16x3 features. One CTA per (book, 64 rows). 256 threads.
//  1. load x fp32 -> split to smem XA + row sumsq -> write g_xh/g_xl (xn split)
//  2. logits = x @ mlp   (bf16x3, B chunks streamed through smem)
//  3. softmax -> xc to out + xc split to XA
//  4. s = xc @ cbT       (bf16x3)
//  5. row norms -> g_sh/g_sl (sn split)
// ---------------------------------------------------------------------------
#define FLDA 264                 // bf16 smem pitch (528B: 16B-mult, bank-staggered)
#define FLDL 260                 // fp32 smem pitch
#define F_XA_H 0
#define F_XA_L 33792
#define F_BB_H 67584
#define F_BB_L 101376
#define F_LL   135168
#define F_DYN  (F_LL + 64 * FLDL * 4)   // 201728

__global__ void __launch_bounds__(256) k_feat(const float* __restrict__ input,
                                              float* __restrict__ out) {
    extern __shared__ __align__(16) char fsm[];
    __nv_bfloat16* XH = (__nv_bfloat16*)(fsm + F_XA_H);
    __nv_bfloat16* XL = (__nv_bfloat16*)(fsm + F_XA_L);
    __nv_bfloat16* BH = (__nv_bfloat16*)(fsm + F_BB_H);
    __nv_bfloat16* BL = (__nv_bfloat16*)(fsm + F_BB_L);
    float*         LL = (float*)(fsm + F_LL);
    __shared__ float part[64][4];
    __shared__ float rinv[64];

    int tid = threadIdx.x, wid = tid >> 5, lane = tid & 31;
    int n0 = blockIdx.x * 64;
    int b  = blockIdx.y;

    // ---- phase 1: load x, split into XA, per-row sumsq
    {
        int r = tid >> 2, q = tid & 3;
        const float* srcp = input + (size_t)(n0 + r) * IN_F + b * LW + q * 64;
        float ss = 0.0f;
        #pragma unroll
        for (int j = 0; j < 16; j++) {
            float4 v = *(const float4*)(srcp + j * 4);
            __align__(8) __nv_bfloat16 h4[4], l4[4];
            split_bf16(v.x, h4[0], l4[0]); split_bf16(v.y, h4[1], l4[1]);
            split_bf16(v.z, h4[2], l4[2]); split_bf16(v.w, h4[3], l4[3]);
            int c = q * 64 + j * 4;
            *(uint2*)&XH[r * FLDA + c] = *(uint2*)h4;
            *(uint2*)&XL[r * FLDA + c] = *(uint2*)l4;
            ss += v.x*v.x + v.y*v.y + v.z*v.z + v.w*v.w;
        }
        part[r][q] = ss;
    }
    __syncthreads();
    if (tid < 64)
        rinv[tid] = 1.0f / fmaxf(sqrtf(part[tid][0] + part[tid][1] +
                                       part[tid][2] + part[tid][3]), EPS);
    __syncthreads();

    // ---- phase 2: write normalized-x splits to global (re-read x, L2-hot)
    {
        int r = tid >> 2, q = tid & 3;
        float iv = rinv[r];
        const float* srcp = input + (size_t)(n0 + r) * IN_F + b * LW + q * 64;
        size_t go = ((size_t)b * N_ROWS + n0 + r) * LW + q * 64;
        #pragma unroll
        for (int j = 0; j < 16; j++) {
            float4 v = *(const float4*)(srcp + j * 4);
            __align__(8) __nv_bfloat16 h4[4], l4[4];
            split_bf16(v.x * iv, h4[0], l4[0]); split_bf16(v.y * iv, h4[1], l4[1]);
            split_bf16(v.z * iv, h4[2], l4[2]); split_bf16(v.w * iv, h4[3], l4[3]);
            *(uint2*)(g_xh + go + j * 4) = *(uint2*)h4;
            *(uint2*)(g_xl + go + j * 4) = *(uint2*)l4;
        }
    }

    int wm = wid >> 2;   // 0..1 : 32-row block
    int wn = wid & 3;    // 0..3 : 64-col block
    wmma::fragment<wmma::accumulator, 16, 16, 16, float> acc[2][4];

    // ================= GEMM 1: logits = x @ mlp =================
    #pragma unroll
    for (int im = 0; im < 2; im++)
        #pragma unroll
        for (int jn = 0; jn < 4; jn++) wmma::fill_fragment(acc[im][jn], 0.0f);

    for (int kc = 0; kc < 4; kc++) {
        __syncthreads();
        const __nv_bfloat16* gbh = g_mh + (size_t)b * LW * WORDS + (size_t)kc * 64 * WORDS;
        const __nv_bfloat16* gbl = g_ml + (size_t)b * LW * WORDS + (size_t)kc * 64 * WORDS;
        #pragma unroll
        for (int j = 0; j < 8; j++) {
            int u = j * 256 + tid, row = u >> 5, seg = u & 31;
            *(uint4*)&BH[row * FLDA + seg * 8] = *(const uint4*)(gbh + row * 256 + seg * 8);
            *(uint4*)&BL[row * FLDA + seg * 8] = *(const uint4*)(gbl + row * 256 + seg * 8);
        }
        __syncthreads();
        #pragma unroll
        for (int k = 0; k < 4; k++) {
            wmma::fragment<wmma::matrix_a, 16, 16, 16, __nv_bfloat16, wmma::row_major> ah[2], al[2];
            #pragma unroll
            for (int im = 0; im < 2; im++) {
                int r0 = wm * 32 + im * 16;
                wmma::load_matrix_sync(ah[im], XH + r0 * FLDA + kc * 64 + k * 16, FLDA);
                wmma::load_matrix_sync(al[im], XL + r0 * FLDA + kc * 64 + k * 16, FLDA);
            }
            #pragma unroll
            for (int jn = 0; jn < 4; jn++) {
                int c0 = wn * 64 + jn * 16;
                wmma::fragment<wmma::matrix_b, 16, 16, 16, __nv_bfloat16, wmma::row_major> bh, bl;
                wmma::load_matrix_sync(bh, BH + (k * 16) * FLDA + c0, FLDA);
                wmma::load_matrix_sync(bl, BL + (k * 16) * FLDA + c0, FLDA);
                #pragma unroll
                for (int im = 0; im < 2; im++) {
                    wmma::mma_sync(acc[im][jn], ah[im], bh, acc[im][jn]);
                    wmma::mma_sync(acc[im][jn], ah[im], bl, acc[im][jn]);
                    wmma::mma_sync(acc[im][jn], al[im], bh, acc[im][jn]);
                }
            }
        }
    }
    __syncthreads();
    #pragma unroll
    for (int im = 0; im < 2; im++)
        #pragma unroll
        for (int jn = 0; jn < 4; jn++)
            wmma::store_matrix_sync(LL + (wm * 32 + im * 16) * FLDL + wn * 64 + jn * 16,
                                    acc[im][jn], FLDL, wmma::mem_row_major);
    __syncthreads();

    // ---- softmax per row; lane owns 8 contiguous cols; xc -> out + XA splits
    #pragma unroll
    for (int rr = 0; rr < 8; rr++) {
        int r = wid * 8 + rr;
        float4 va = *(float4*)&LL[r * FLDL + lane * 8];
        float4 vb = *(float4*)&LL[r * FLDL + lane * 8 + 4];
        float v[8] = {va.x, va.y, va.z, va.w, vb.x, vb.y, vb.z, vb.w};
        float mx = v[0];
        #pragma unroll
        for (int j = 1; j < 8; j++) mx = fmaxf(mx, v[j]);
        #pragma unroll
        for (int off = 16; off; off >>= 1) mx = fmaxf(mx, __shfl_xor_sync(0xffffffffu, mx, off));
        float sm = 0.0f;
        #pragma unroll
        for (int j = 0; j < 8; j++) { v[j] = expf(v[j] - mx); sm += v[j]; }
        #pragma unroll
        for (int off = 16; off; off >>= 1) sm += __shfl_xor_sync(0xffffffffu, sm, off);
        float inv = 1.0f / sm;
        __align__(16) __nv_bfloat16 h8[8], l8[8];
        #pragma unroll
        for (int j = 0; j < 8; j++) { v[j] *= inv; split_bf16(v[j], h8[j], l8[j]); }
        float* po = out + OFF3 + (size_t)(n0 + r) * (BOOKS * WORDS) + b * WORDS + lane * 8;
        *(float4*)po       = make_float4(v[0], v[1], v[2], v[3]);
        *(float4*)(po + 4) = make_float4(v[4], v[5], v[6], v[7]);
        *(uint4*)&XH[r * FLDA + lane * 8] = *(uint4*)h8;
        *(uint4*)&XL[r * FLDA + lane * 8] = *(uint4*)l8;
    }
    __syncthreads();

    // ================= GEMM 2: s = xc @ cbT =================
    #pragma unroll
    for (int im = 0; im < 2; im++)
        #pragma unroll
        for (int jn = 0; jn < 4; jn++) wmma::fill_fragment(acc[im][jn], 0.0f);

    for (int kc = 0; kc < 4; kc++) {
        __syncthreads();
        const __nv_bfloat16* gbh = g_cbTh + (size_t)b * WORDS * LW + (size_t)kc * 64 * LW;
        const __nv_bfloat16* gbl = g_cbTl + (size_t)b * WORDS * LW + (size_t)kc * 64 * LW;
        #pragma unroll
        for (int j = 0; j < 8; j++) {
            int u = j * 256 + tid, row = u >> 5, seg = u & 31;
            *(uint4*)&BH[row * FLDA + seg * 8] = *(const uint4*)(gbh + row * 256 + seg * 8);
            *(uint4*)&BL[row * FLDA + seg * 8] = *(const uint4*)(gbl + row * 256 + seg * 8);
        }
        __syncthreads();
        #pragma unroll
        for (int k = 0; k < 4; k++) {
            wmma::fragment<wmma::matrix_a, 16, 16, 16, __nv_bfloat16, wmma::row_major> ah[2], al[2];
            #pragma unroll
            for (int im = 0; im < 2; im++) {
                int r0 = wm * 32 + im * 16;
                wmma::load_matrix_sync(ah[im], XH + r0 * FLDA + kc * 64 + k * 16, FLDA);
                wmma::load_matrix_sync(al[im], XL + r0 * FLDA + kc * 64 + k * 16, FLDA);
            }
            #pragma unroll
            for (int jn = 0; jn < 4; jn++) {
                int c0 = wn * 64 + jn * 16;
                wmma::fragment<wmma::matrix_b, 16, 16, 16, __nv_bfloat16, wmma::row_major> bh, bl;
                wmma::load_matrix_sync(bh, BH + (k * 16) * FLDA + c0, FLDA);
                wmma::load_matrix_sync(bl, BL + (k * 16) * FLDA + c0, FLDA);
                #pragma unroll
                for (int im = 0; im < 2; im++) {
                    wmma::mma_sync(acc[im][jn], ah[im], bh, acc[im][jn]);
                    wmma::mma_sync(acc[im][jn], ah[im], bl, acc[im][jn]);
                    wmma::mma_sync(acc[im][jn], al[im], bh, acc[im][jn]);
                }
            }
        }
    }
    __syncthreads();
    #pragma unroll
    for (int im = 0; im < 2; im++)
        #pragma unroll
        for (int jn = 0; jn < 4; jn++)
            wmma::store_matrix_sync(LL + (wm * 32 + im * 16) * FLDL + wn * 64 + jn * 16,
                                    acc[im][jn], FLDL, wmma::mem_row_major);
    __syncthreads();

    // ---- s row norms -> g_sh/g_sl
    #pragma unroll
    for (int rr = 0; rr < 8; rr++) {
        int r = wid * 8 + rr;
        float4 va = *(float4*)&LL[r * FLDL + lane * 8];
        float4 vb = *(float4*)&LL[r * FLDL + lane * 8 + 4];
        float v[8] = {va.x, va.y, va.z, va.w, vb.x, vb.y, vb.z, vb.w};
        float ss = 0.0f;
        #pragma unroll
        for (int j = 0; j < 8; j++) ss += v[j] * v[j];
        #pragma unroll
        for (int off = 16; off; off >>= 1) ss += __shfl_xor_sync(0xffffffffu, ss, off);
        float inv = 1.0f / fmaxf(sqrtf(ss), EPS);
        __align__(16) __nv_bfloat16 h8[8], l8[8];
        #pragma unroll
        for (int j = 0; j < 8; j++) split_bf16(v[j] * inv, h8[j], l8[j]);
        size_t go = ((size_t)b * N_ROWS + n0 + r) * LW + lane * 8;
        *(uint4*)(g_sh + go) = *(uint4*)h8;
        *(uint4*)(g_sl + go) = *(uint4*)l8;
    }
}

// ---------------------------------------------------------------------------
// Kernel 4: WMMA bf16x3 dual GEMM + fused epilogue (unchanged from R4).
// ---------------------------------------------------------------------------
#define LDT      72
#define TILE_E   (128 * LDT)
#define TILE_B   (TILE_E * 2)
#define STAGE_E  (6 * TILE_E)
#define STAGE_B  (6 * TILE_B)
#define DYN_SMEM (2 * STAGE_B)
#define DPITCH   136
#define REG2     (128 * DPITCH)

__global__ void __launch_bounds__(256, 1) k_gemm_wm(const int* __restrict__ label,
                                                    float* __restrict__ out) {
    extern __shared__ __align__(16) char dsm[];
    __nv_bfloat16* smt = (__nv_bfloat16*)dsm;
    __shared__ int s_lbl[128];

    int tid = threadIdx.x;
    int wid = tid >> 5, lane = tid & 31;
    int nt = blockIdx.x, mt = blockIdx.y, b = blockIdx.z;
    uint32_t smbase = smem_u32(dsm);

    if (tid < 128) s_lbl[tid] = label[mt * 128 + tid];

    const char* pXH = (const char*)(g_xh + ((size_t)b * N_ROWS + mt * 128) * LW);
    const char* pXL = (const char*)(g_xl + ((size_t)b * N_ROWS + mt * 128) * LW);
    const char* pSH = (const char*)(g_sh + ((size_t)b * N_ROWS + mt * 128) * LW);
    const char* pSL = (const char*)(g_sl + ((size_t)b * N_ROWS + mt * 128) * LW);
    const char* pWH = (const char*)(g_wh + ((size_t)b * OUT_F  + nt * 128) * LW);
    const char* pWL = (const char*)(g_wl + ((size_t)b * OUT_F  + nt * 128) * LW);

#define LD1TILE(ptr, t, c_, st_) { \
    _Pragma("unroll") for (int j = 0; j < 4; j++) { \
        int u = j * 256 + tid; int row = u >> 3, seg = u & 7; \
        uint32_t dst = smbase + (st_) * STAGE_B + (t) * TILE_B + row * 144 + seg * 16; \
        const char* src = (ptr) + (size_t)row * 512 + (c_) * 128 + seg * 16; \
        CP_ASYNC16(dst, src); } }
#define LOAD_CHUNK(c_, st_) { \
    LD1TILE(pXH, 0, c_, st_); LD1TILE(pXL, 1, c_, st_); \
    LD1TILE(pSH, 2, c_, st_); LD1TILE(pSL, 3, c_, st_); \
    LD1TILE(pWH, 4, c_, st_); LD1TILE(pWL, 5, c_, st_); \
    CP_COMMIT(); }

    wmma::fragment<wmma::accumulator, 16, 16, 16, float> acc1[2][4], acc2[2][4];
    #pragma unroll
    for (int im = 0; im < 2; im++)
        #pragma unroll
        for (int jn = 0; jn < 4; jn++) {
            wmma::fill_fragment(acc1[im][jn], 0.0f);
            wmma::fill_fragment(acc2[im][jn], 0.0f);
        }

    int wm = wid & 3;
    int wn = wid >> 2;

    LOAD_CHUNK(0, 0);
    LOAD_CHUNK(1, 1);

    #pragma unroll
    for (int c = 0; c < 4; c++) {
        if (c < 3) { CP_WAIT(1); } else { CP_WAIT(0); }
        __syncthreads();
        {
            int st = c & 1;
            const __nv_bfloat16* base = smt + st * STAGE_E;
            const __nv_bfloat16* tXH = base;
            const __nv_bfloat16* tXL = base + TILE_E;
            const __nv_bfloat16* tSH = base + 2 * TILE_E;
            const __nv_bfloat16* tSL = base + 3 * TILE_E;
            const __nv_bfloat16* tWH = base + 4 * TILE_E;
            const __nv_bfloat16* tWL = base + 5 * TILE_E;
            #pragma unroll
            for (int k = 0; k < 4; k++) {
                wmma::fragment<wmma::matrix_a, 16, 16, 16, __nv_bfloat16, wmma::row_major>
                    axh[2], axl[2], ash[2], asl[2];
                #pragma unroll
                for (int im = 0; im < 2; im++) {
                    int r0 = wm * 32 + im * 16;
                    wmma::load_matrix_sync(axh[im], tXH + r0 * LDT + k * 16, LDT);
                    wmma::load_matrix_sync(axl[im], tXL + r0 * LDT + k * 16, LDT);
                    wmma::load_matrix_sync(ash[im], tSH + r0 * LDT + k * 16, LDT);
                    wmma::load_matrix_sync(asl[im], tSL + r0 * LDT + k * 16, LDT);
                }
                #pragma unroll
                for (int jn = 0; jn < 4; jn++) {
                    int c0 = wn * 64 + jn * 16;
                    wmma::fragment<wmma::matrix_b, 16, 16, 16, __nv_bfloat16, wmma::col_major> bwh, bwl;
                    wmma::load_matrix_sync(bwh, tWH + c0 * LDT + k * 16, LDT);
                    wmma::load_matrix_sync(bwl, tWL + c0 * LDT + k * 16, LDT);
                    #pragma unroll
                    for (int im = 0; im < 2; im++) {
                        wmma::mma_sync(acc1[im][jn], axh[im], bwh, acc1[im][jn]);
                        wmma::mma_sync(acc1[im][jn], axh[im], bwl, acc1[im][jn]);
                        wmma::mma_sync(acc1[im][jn], axl[im], bwh, acc1[im][jn]);
                        wmma::mma_sync(acc2[im][jn], ash[im], bwh, acc2[im][jn]);
                        wmma::mma_sync(acc2[im][jn], ash[im], bwl, acc2[im][jn]);
                        wmma::mma_sync(acc2[im][jn], asl[im], bwh, acc2[im][jn]);
                    }
                }
            }
        }
        __syncthreads();
        if (c + 2 < 4) { LOAD_CHUNK(c + 2, c & 1); }
    }

    float* D = (float*)dsm;
    #pragma unroll
    for (int im = 0; im < 2; im++)
        #pragma unroll
        for (int jn = 0; jn < 4; jn++) {
            int r0 = wm * 32 + im * 16;
            int c0 = wn * 64 + jn * 16;
            wmma::store_matrix_sync(D + (size_t)r0 * DPITCH + c0, acc1[im][jn],
                                    DPITCH, wmma::mem_row_major);
            wmma::store_matrix_sync(D + REG2 + (size_t)r0 * DPITCH + c0, acc2[im][jn],
                                    DPITCH, wmma::mem_row_major);
        }
    __syncthreads();

    {
        int colq = lane;
        for (int r0 = wid; r0 < 128; r0 += 8) {
            int lv = s_lbl[r0];
            int o0 = nt * 128 + colq * 4;
            size_t basep = (size_t)(mt * 128 + r0) * (BOOKS * OUT_F) + (size_t)b * OUT_F + o0;
            float4 v1 = *(float4*)&D[(size_t)r0 * DPITCH + colq * 4];
            float4 v2 = *(float4*)&D[REG2 + (size_t)r0 * DPITCH + colq * 4];
            float* p1 = &v1.x; float* p2 = &v2.x;
            #pragma unroll
            for (int j = 0; j < 4; j++) {
                float m = (o0 + j == lv) ? MARGIN : 0.0f;
                p1[j] = SC * (fminf(fmaxf(p1[j], -1.0f), 1.0f) - m);
                p2[j] = SC * (fminf(fmaxf(p2[j], -1.0f), 1.0f) - m);
            }
            *(float4*)(out + basep)        = v1;
            *(float4*)(out + OFF2 + basep) = v2;
        }
    }
}

// ---------------------------------------------------------------------------
extern "C" void kernel_launch(void* const* d_in, const int* in_sizes, int n_in,
                              void* d_out, int out_size) {
    const float* input  = (const float*)d_in[0];
    const int*   label  = (const int*)d_in[1];
    const float* weight = (const float*)d_in[2];
    const float* mlp    = (const float*)d_in[3];
    const float* cb     = (const float*)d_in[4];
    float*       out    = (float*)d_out;
    (void)in_sizes; (void)n_in; (void)out_size;

    cudaFuncSetAttribute(k_gemm_wm, cudaFuncAttributeMaxDynamicSharedMemorySize, DYN_SMEM);
    cudaFuncSetAttribute(k_feat, cudaFuncAttributeMaxDynamicSharedMemorySize, F_DYN);

    k_norm_w<<<BOOKS * OUT_F / 8, 256>>>(weight);
    k_split_mlp<<<BOOKS * LW * WORDS / 1024, 256>>>(mlp);
    k_transpose_cb<<<dim3(LW / 32, WORDS / 32, BOOKS), dim3(32, 8)>>>(cb);
    k_feat<<<dim3(N_ROWS / 64, BOOKS), 256, F_DYN>>>(input, out);
    k_gemm_wm<<<dim3(OUT_F / 128, N_ROWS / 128, BOOKS), 256, DYN_SMEM>>>(label, out);
}